// round 17
// baseline (speedup 1.0000x reference)
#include <cuda_runtime.h>
#include <cuda_fp16.h>
#include <math.h>
#include <stdint.h>

// Scratch. [B,S,S], B=4,S=160. q1T and fp16 scores use padded row stride SP=192.
#define MAXQ  102400
#define MAXQP 122880               // B*S rows * 192
#define MAXR  1024
#define MAXEP 19660800             // B*S*S rows * 192 halves
__device__ __align__(16)  float g_q1 [2][MAXQ];    // Q1, rows (b,x) stride S
__device__ __align__(128) float g_q1T[2][MAXQP];   // Q1 transposed, rows (b,x) stride 192
__device__ int   g_excl[MAXQ];
__device__ int   g_ecnt[MAXR];
// fp16 score copies, row stride 192 halves (384 B, 128B-aligned rows)
__device__ __align__(128) __half g_hss[MAXEP];
__device__ __align__(128) __half g_hsc[MAXEP];
__device__ __align__(128) __half g_hsg[MAXEP];

// Pre-pass: build per-(b,h) exclusion list.
__global__ void excl_build_kernel(const int* __restrict__ mask, int S)
{
    __shared__ int cnt;
    int t = threadIdx.x;
    int h = blockIdx.x % S;
    int b = blockIdx.x / S;
    int row = b * S + h;
    if (t == 0) cnt = 0;
    __syncthreads();
    if (t < S) {
        bool ex = (mask[(b * S + t) * S + h] == 0) || (t == h);
        if (ex) {
            int slot = atomicAdd(&cnt, 1);
            g_excl[row * S + slot] = t;
        }
    }
    __syncthreads();
    if (t == 0) g_ecnt[row] = cnt;
}

// Zero the pad regions (fp16 rows [S,SP) and q1T rows [S,SP)); S==160 path only.
__global__ void pad_zero_kernel(int S, int SP, int R, int BR)
{
    int i = blockIdx.x * blockDim.x + threadIdx.x;
    int padu = (SP - S) / 4;           // 8 uint2 per fp16 row
    if (i < R * padu) {
        int row = i / padu, j = i % padu;
        uint2 z; z.x = 0; z.y = 0;
        ((uint2*)(g_hss + (long)row * SP + S))[j] = z;
        ((uint2*)(g_hsc + (long)row * SP + S))[j] = z;
        ((uint2*)(g_hsg + (long)row * SP + S))[j] = z;
    }
    int padf = (SP - S) / 4;           // 8 float4 per q1T row
    if (i < BR * padf) {
        int row = i / padf, j = i % padf;
        float4 z = make_float4(0.f, 0.f, 0.f, 0.f);
        ((float4*)(g_q1T[0] + (long)row * SP + S))[j] = z;
        ((float4*)(g_q1T[1] + (long)row * SP + S))[j] = z;
    }
}

// ============================================================================
// Iter 1 (Q1 = 0.5), fused fp32->fp16 conversion. R13 body; writes use SP stride.
// ============================================================================
template<int SS>
__global__ void __launch_bounds__(256, 4)
mfvi_iter0_conv(const float* __restrict__ se,
                const float* __restrict__ ss,
                const float* __restrict__ sc,
                const float* __restrict__ sg,
                const int* __restrict__ mask,
                int outbuf)
{
    constexpr int SP = SS + 32;    // 192
    constexpr int HT = 32;
    constexpr int NTILE = SS / HT;
    constexpr int FV = SS >> 2;
    constexpr int KK = FV / 8;     // 5

    int blk = blockIdx.x;
    int htile = blk % NTILE;
    int m     = (blk / NTILE) % SS;
    int b     = blk / (NTILE * SS);
    int warp = threadIdx.x >> 5, lane = threadIdx.x & 31;
    int g = lane >> 3, li = lane & 7;
    int h = htile * HT + warp * 4 + g;

    const long sbase = (((long)(b * SS + m)) * SS + h) * SS;
    const long pbase = (((long)(b * SS + m)) * SS + h) * SP;
    const float4* p_ss = (const float4*)(ss + sbase);
    const float4* p_sc = (const float4*)(sc + sbase);
    const float4* p_sg = (const float4*)(sg + sbase);
    uint2* w_ss = (uint2*)(g_hss + pbase);
    uint2* w_sc = (uint2*)(g_hsc + pbase);
    uint2* w_sg = (uint2*)(g_hsg + pbase);

    float acc = 0.f;
    #pragma unroll
    for (int k = 0; k < KK; k++) {
        int v = li + 8 * k;
        float4 vss = __ldcs(p_ss + v);
        float4 vsc = __ldcs(p_sc + v);
        float4 vsg = __ldcs(p_sg + v);
        #pragma unroll
        for (int j = 0; j < 4; j++)
            acc += (&vss.x)[j] + (&vsc.x)[j] + (&vsg.x)[j];
        __half2 a0 = __floats2half2_rn(vss.x, vss.y), a1 = __floats2half2_rn(vss.z, vss.w);
        __half2 b0 = __floats2half2_rn(vsc.x, vsc.y), b1 = __floats2half2_rn(vsc.z, vsc.w);
        __half2 c0 = __floats2half2_rn(vsg.x, vsg.y), c1 = __floats2half2_rn(vsg.z, vsg.w);
        uint2 u;
        u.x = *(unsigned*)&a0; u.y = *(unsigned*)&a1; __stcs(w_ss + v, u);
        u.x = *(unsigned*)&b0; u.y = *(unsigned*)&b1; __stcs(w_sc + v, u);
        u.x = *(unsigned*)&c0; u.y = *(unsigned*)&c1; __stcs(w_sg + v, u);
    }
    acc += __shfl_down_sync(0xffffffffu, acc, 4, 8);
    acc += __shfl_down_sync(0xffffffffu, acc, 2, 8);
    acc += __shfl_down_sync(0xffffffffu, acc, 1, 8);

    if (li == 0) {
        int idx = (b * SS + m) * SS + h;
        float f = 0.f;
        if (mask[idx] != 0) {
            acc *= 0.5f;
            int row = b * SS + h;
            int cnt = g_ecnt[row];
            for (int i = 0; i < cnt; i++) {
                int t = g_excl[row * SS + i];
                acc -= 0.5f * (ss[sbase + t] + sc[sbase + t] + sg[sbase + t]);
            }
            if (m != h)
                acc -= 0.5f * (ss[sbase + m] + sc[sbase + m] + sg[sbase + m]);
            f = acc;
        }
        float q = se[idx] + f;
        float q1v = 1.f / (1.f + expf(-q));
        g_q1 [outbuf][idx] = q1v;
        g_q1T[outbuf][(long)(b * SS + h) * SP + m] = q1v;
    }
}

// unpack 8 halves (uint4) -> 8 floats
__device__ __forceinline__ void h8f(const uint4& u, float* f) {
    float2 t;
    t = __half22float2(*(const __half2*)&u.x); f[0] = t.x; f[1] = t.y;
    t = __half22float2(*(const __half2*)&u.y); f[2] = t.x; f[3] = t.y;
    t = __half22float2(*(const __half2*)&u.z); f[4] = t.x; f[5] = t.y;
    t = __half22float2(*(const __half2*)&u.w); f[6] = t.x; f[7] = t.y;
}

// ============================================================================
// Iters 2/3: padded fp16 streams, 8-lane groups, 4 rows/warp, 16 rows/block.
// Every score LDG.128 covers one aligned 128B line per row (nL=4/warp).
// ============================================================================
template<int FINAL, int SS>
__global__ void __launch_bounds__(128)
mfvi_iter_h(const float* __restrict__ se,
            const int* __restrict__ mask,
            float* __restrict__ out,
            int parity)
{
    constexpr int SP = SS + 32;    // 192
    constexpr int HT = 16;         // rows per block (4 warps x 4 rows)
    constexpr int NTILE = SS / HT; // 10
    constexpr int CH = SP / 8;     // 24 uint4 chunks per padded fp16 row
    constexpr int KK = CH / 8;     // 3 per 8-lane group

    int blk = blockIdx.x;
    int htile = blk % NTILE;
    int m     = (blk / NTILE) % SS;
    int b     = blk / (NTILE * SS);
    int tid = threadIdx.x;
    int w = tid >> 5, lane = tid & 31;
    int g = lane >> 3, li8 = lane & 7;
    int rt = w * 4 + g;
    int h = htile * HT + rt;

    extern __shared__ float smbuf[];
    float* sm_row = smbuf;         // Q1[b,m,t]   [SP], pad zeroed
    float* sm_col = smbuf + SP;    // Q1[b,t,m]   [SP], pad zeroed (from padded q1T)

    const float* __restrict__ q1_in  = g_q1 [parity & 1];
    const float* __restrict__ q1T_in = g_q1T[parity & 1];

    {
        const float4* r4 = (const float4*)(q1_in  + (b * SS + m) * SS);          // 40 valid
        const float4* c4 = (const float4*)(q1T_in + (long)(b * SS + m) * SP);    // 48 incl zero pad
        for (int i = tid; i < SP / 4; i += 128)
            ((float4*)sm_col)[i] = c4[i];
        for (int i = tid; i < SP / 4; i += 128) {
            float4 v = (i < SS / 4) ? r4[i] : make_float4(0.f, 0.f, 0.f, 0.f);
            ((float4*)sm_row)[i] = v;
        }
        __syncthreads();
    }

    const long pbase = (((long)(b * SS + m)) * SS + h) * SP;   // fp16 padded row
    const long hbase = (long)(b * SS + h) * SP;                // q1T padded row
    const uint4* pss = (const uint4*)(g_hss + pbase);
    const uint4* psc = (const uint4*)(g_hsc + pbase);
    const uint4* psg = (const uint4*)(g_hsg + pbase);
    const float4* pqa = (const float4*)(q1T_in + hbase);
    const float4* srow = (const float4*)sm_row;
    const float4* scol = (const float4*)sm_col;

    float accA = 0.f, accB = 0.f, accC = 0.f;
    #pragma unroll
    for (int k = 0; k < KK; k++) {
        int c = li8 + 8 * k;       // uint4 chunk; t0 = 8c
        uint4 ua = __ldcs(pss + c);
        uint4 ub = __ldcs(psc + c);
        uint4 uc = __ldcs(psg + c);
        float4 q0 = __ldg(pqa + 2 * c), q1v = __ldg(pqa + 2 * c + 1);
        float4 r0 = srow[2 * c], r1 = srow[2 * c + 1];
        float4 c0 = scol[2 * c], c1 = scol[2 * c + 1];
        float fa[8], fb[8], fc[8];
        h8f(ua, fa); h8f(ub, fb); h8f(uc, fc);
        float qv[8] = {q0.x, q0.y, q0.z, q0.w, q1v.x, q1v.y, q1v.z, q1v.w};
        float rv[8] = {r0.x, r0.y, r0.z, r0.w, r1.x, r1.y, r1.z, r1.w};
        float cv[8] = {c0.x, c0.y, c0.z, c0.w, c1.x, c1.y, c1.z, c1.w};
        #pragma unroll
        for (int j = 0; j < 8; j++) {
            accA += fa[j] * qv[j];
            accB += fb[j] * rv[j];
            accC += fc[j] * cv[j];
        }
    }

    float acc = (accA + accB) + accC;
    acc += __shfl_down_sync(0xffffffffu, acc, 4, 8);
    acc += __shfl_down_sync(0xffffffffu, acc, 2, 8);
    acc += __shfl_down_sync(0xffffffffu, acc, 1, 8);

    if (li8 == 0) {
        int idx = (b * SS + m) * SS + h;
        float f = 0.f;
        if (mask[idx] != 0) {
            int row = b * SS + h;
            int cnt = g_ecnt[row];
            for (int i = 0; i < cnt; i++) {
                int t = g_excl[row * SS + i];
                acc -= __half2float(g_hss[pbase + t]) * q1T_in[hbase + t]
                     + __half2float(g_hsc[pbase + t]) * sm_row[t]
                     + __half2float(g_hsg[pbase + t]) * sm_col[t];
            }
            if (m != h)
                acc -= __half2float(g_hss[pbase + m]) * q1T_in[hbase + m]
                     + __half2float(g_hsc[pbase + m]) * sm_row[m]
                     + __half2float(g_hsg[pbase + m]) * sm_col[m];
            f = acc;
        }
        float q = se[idx] + f;
        if (FINAL) {
            out[(long)idx * 2 + 0] = 1.f / (1.f + expf(q));
            out[(long)idx * 2 + 1] = 1.f / (1.f + expf(-q));
        } else {
            float q1v = 1.f / (1.f + expf(-q));
            int ob = (parity ^ 1) & 1;
            g_q1 [ob][idx] = q1v;
            g_q1T[ob][(long)(b * SS + h) * SP + m] = q1v;
        }
    }
}

// ============================================================================
// Generic fp32 fallback for S != 160 (unpadded stride-S indexing throughout)
// ============================================================================
__global__ void __launch_bounds__(256, 4)
mfvi_iter0_gen(const float* __restrict__ se,
               const float* __restrict__ ss,
               const float* __restrict__ sc,
               const float* __restrict__ sg,
               const int* __restrict__ mask,
               int S, int outbuf)
{
    const int HT = 32;
    int ntile = (S + HT - 1) / HT;
    int blk = blockIdx.x;
    int htile = blk % ntile;
    int m     = (blk / ntile) % S;
    int b     = blk / (ntile * S);
    int warp = threadIdx.x >> 5, lane = threadIdx.x & 31;
    int g = lane >> 3, li = lane & 7;
    int h = htile * HT + warp * 4 + g;
    bool valid = (h < S);
    const long sbase = (((long)(b * S + m)) * S + h) * S;

    float acc = 0.f;
    if (valid) {
        for (int t = li; t < S; t += 8)
            acc += ss[sbase + t] + sc[sbase + t] + sg[sbase + t];
    }
    acc += __shfl_down_sync(0xffffffffu, acc, 4, 8);
    acc += __shfl_down_sync(0xffffffffu, acc, 2, 8);
    acc += __shfl_down_sync(0xffffffffu, acc, 1, 8);
    if (li == 0 && valid) {
        int idx = (b * S + m) * S + h;
        float f = 0.f;
        if (mask[idx] != 0) {
            acc *= 0.5f;
            int row = b * S + h;
            int cnt = g_ecnt[row];
            for (int i = 0; i < cnt; i++) {
                int t = g_excl[row * S + i];
                acc -= 0.5f * (ss[sbase + t] + sc[sbase + t] + sg[sbase + t]);
            }
            if (m != h)
                acc -= 0.5f * (ss[sbase + m] + sc[sbase + m] + sg[sbase + m]);
            f = acc;
        }
        float q = se[idx] + f;
        float q1v = 1.f / (1.f + expf(-q));
        g_q1 [outbuf][idx] = q1v;
        g_q1T[outbuf][(b * S + h) * S + m] = q1v;
    }
}

template<int FINAL>
__global__ void __launch_bounds__(256, 4)
mfvi_fallback(const float* __restrict__ se,
              const float* __restrict__ ss,
              const float* __restrict__ sc,
              const float* __restrict__ sg,
              const int* __restrict__ mask,
              float* __restrict__ out,
              int S, int parity)
{
    const int HT = 32;
    int ntile = (S + HT - 1) / HT;
    int blk = blockIdx.x;
    int htile = blk % ntile;
    int m     = (blk / ntile) % S;
    int b     = blk / (ntile * S);
    int warp = threadIdx.x >> 5, lane = threadIdx.x & 31;
    int g = lane >> 3, li = lane & 7;
    int h = htile * HT + warp * 4 + g;

    extern __shared__ float smbuf[];
    float* sm_row = smbuf;
    float* sm_col = smbuf + S;
    const float* __restrict__ q1_in  = g_q1 [parity & 1];
    const float* __restrict__ q1T_in = g_q1T[parity & 1];
    for (int i = threadIdx.x; i < 2 * S; i += blockDim.x) {
        if (i < S) sm_row[i] = q1_in[(b * S + m) * S + i];
        else       sm_col[i - S] = q1T_in[(b * S + m) * S + (i - S)];
    }
    __syncthreads();

    bool valid = (h < S);
    const long sbase = (((long)(b * S + m)) * S + h) * S;
    const long hbase = ((long)(b * S + h)) * S;
    float acc = 0.f;
    if (valid) {
        for (int t = li; t < S; t += 8)
            acc += ss[sbase + t] * q1T_in[hbase + t]
                 + sc[sbase + t] * sm_row[t]
                 + sg[sbase + t] * sm_col[t];
    }
    acc += __shfl_down_sync(0xffffffffu, acc, 4, 8);
    acc += __shfl_down_sync(0xffffffffu, acc, 2, 8);
    acc += __shfl_down_sync(0xffffffffu, acc, 1, 8);
    if (li == 0 && valid) {
        int idx = (b * S + m) * S + h;
        float f = 0.f;
        if (mask[idx] != 0) {
            int row = b * S + h;
            int cnt = g_ecnt[row];
            for (int i = 0; i < cnt; i++) {
                int t = g_excl[row * S + i];
                acc -= ss[sbase + t] * q1T_in[hbase + t]
                     + sc[sbase + t] * sm_row[t]
                     + sg[sbase + t] * sm_col[t];
            }
            if (m != h)
                acc -= ss[sbase + m] * q1T_in[hbase + m]
                     + sc[sbase + m] * sm_row[m]
                     + sg[sbase + m] * sm_col[m];
            f = acc;
        }
        float q = se[idx] + f;
        if (FINAL) {
            out[(long)idx * 2 + 0] = 1.f / (1.f + expf(q));
            out[(long)idx * 2 + 1] = 1.f / (1.f + expf(-q));
        } else {
            float q1v = 1.f / (1.f + expf(-q));
            int ob = (parity ^ 1) & 1;
            g_q1 [ob][idx] = q1v;
            g_q1T[ob][(b * S + h) * S + m] = q1v;
        }
    }
}

extern "C" void kernel_launch(void* const* d_in, const int* in_sizes, int n_in,
                              void* d_out, int out_size)
{
    const float* se = (const float*)d_in[0];
    const float* ss = (const float*)d_in[1];
    const float* sc = (const float*)d_in[2];
    const float* sg = (const float*)d_in[3];
    const int* mask = (const int*)d_in[4];
    float* out = (float*)d_out;

    int BSS = in_sizes[0];                  // B*S*S
    int S = in_sizes[1] / BSS;              // (B*S^3)/(B*S^2)
    int B = BSS / (S * S);

    excl_build_kernel<<<B * S, (S + 31) & ~31>>>(mask, S);

    if (S == 160) {
        const int SP = 192;
        int R = B * S * S, BR = B * S;
        int padu = (SP - S) / 4;
        int npad = R * padu;                // 819200
        pad_zero_kernel<<<(npad + 255) / 256, 256>>>(S, SP, R, BR);

        int ntile0 = S / 32;
        dim3 grid0(B * S * ntile0);
        // iter 1: fp32 sum (Q1=0.5) + fp16 conversion (padded layout) -> buf 0
        mfvi_iter0_conv<160><<<grid0, 256>>>(se, ss, sc, sg, mask, 0);

        int ntileh = S / 16;
        dim3 gridh(B * S * ntileh);
        size_t smemh = 2 * (size_t)SP * sizeof(float);
        // iter 2: fp16 streams, read buf 0, write buf 1
        mfvi_iter_h<0, 160><<<gridh, 128, smemh>>>(se, mask, out, 0);
        // iter 3: fp16 streams, read buf 1, write output
        mfvi_iter_h<1, 160><<<gridh, 128, smemh>>>(se, mask, out, 1);
    } else {
        int ntile = (S + 31) / 32;
        dim3 grid(B * S * ntile);
        size_t smem = 2 * (size_t)S * sizeof(float);
        mfvi_iter0_gen<<<grid, 256>>>(se, ss, sc, sg, mask, S, 0);
        mfvi_fallback<0><<<grid, 256, smem>>>(se, ss, sc, sg, mask, out, S, 0);
        mfvi_fallback<1><<<grid, 256, smem>>>(se, ss, sc, sg, mask, out, S, 1);
    }
}